// round 5
// baseline (speedup 1.0000x reference)
#include <cuda_runtime.h>
#include <cstdint>
#include <cstddef>

#define HID   128
#define OUTD  256
#define NT    32          // nodes per MLP block
#define NTP   36          // padded node stride in smem (16B-aligned rows, de-conflicted stores)
#define N_NODES_MAX 50000

typedef unsigned long long ull;

// Scratch: node accumulator [num_nodes, 128]. Static device array (no allocs allowed).
__device__ float g_h128[(size_t)N_NODES_MAX * HID];
__device__ int   g_is64;

// ---------------------------------------------------------------------------
// Kernel 0: zero accumulator + detect index dtype (int64 vs int32).
// If the data is really int32, reading it as int64 gives values >= 2^32 with
// overwhelming probability (indices are < 50000), so 4 in-range samples => int64.
// ---------------------------------------------------------------------------
__global__ void zero_detect_kernel(const void* __restrict__ idx, int num_nodes) {
    size_t total  = (size_t)num_nodes * HID;
    size_t stride = (size_t)gridDim.x * blockDim.x;
    for (size_t j = (size_t)blockIdx.x * blockDim.x + threadIdx.x; j < total; j += stride)
        g_h128[j] = 0.0f;
    if (blockIdx.x == 0 && threadIdx.x == 0) {
        const long long* p = (const long long*)idx;
        int ok = 1;
        #pragma unroll
        for (int k = 0; k < 4; k++) {
            long long v = p[k];
            if (v < 0 || v >= (long long)num_nodes) ok = 0;
        }
        g_is64 = ok;
    }
}

// ---------------------------------------------------------------------------
// Kernel 1: gate + atomic scatter.  One warp per edge.
//   coef[h] = sum_r rbf[e,r] * W_rbf[r,h];  g = coef * x[e,:];  REDG into node row.
// Lane l handles columns 4l..4l+3 (float4).  W_rbf (6x128) cached in smem.
// ---------------------------------------------------------------------------
__global__ void gate_scatter_kernel(const float4* __restrict__ x4,
                                    const float*  __restrict__ rbf,
                                    const void*   __restrict__ idx,
                                    const float*  __restrict__ W_rbf,
                                    int E, int num_nodes) {
    __shared__ __align__(16) float sW[6 * HID];
    for (int j = threadIdx.x; j < 6 * HID; j += blockDim.x) sW[j] = W_rbf[j];
    __syncthreads();

    int lane = threadIdx.x & 31;
    int gw = (blockIdx.x * blockDim.x + threadIdx.x) >> 5;
    if (gw >= E) return;
    int e = gw;

    int node = g_is64 ? (int)(((const long long*)idx)[e])
                      : (((const int*)idx)[e]);

    float r[6];
    #pragma unroll
    for (int q = 0; q < 6; q++) r[q] = __ldg(rbf + (size_t)e * 6 + q);

    float4 c = make_float4(0.f, 0.f, 0.f, 0.f);
    #pragma unroll
    for (int q = 0; q < 6; q++) {
        float4 wv = reinterpret_cast<const float4*>(sW + q * HID)[lane];
        c.x += r[q] * wv.x;  c.y += r[q] * wv.y;
        c.z += r[q] * wv.z;  c.w += r[q] * wv.w;
    }

    float4 xv = __ldg(x4 + (size_t)e * (HID / 4) + lane);
    float* dst = g_h128 + (size_t)node * HID + lane * 4;
    atomicAdd(dst + 0, c.x * xv.x);
    atomicAdd(dst + 1, c.y * xv.y);
    atomicAdd(dst + 2, c.z * xv.z);
    atomicAdd(dst + 3, c.w * xv.w);
}

// ---------------------------------------------------------------------------
// Kernel 2: fused node MLP.  Block = 256 threads (thread t owns output col t),
// 32 nodes per block.  Activations in smem as [k][node] (stride NTP=36) so one
// broadcast LDS.128 yields 4 node-values = 2 packed f32x2 operands.
// Packed fma.rn.f32x2 doubles fp32 FMA throughput vs scalar FFMA (rt 2 -> eff 1).
// ---------------------------------------------------------------------------
__device__ __forceinline__ void fma2(ull& acc, ull a, ull b) {
    asm("fma.rn.f32x2 %0, %1, %2, %0;" : "+l"(acc) : "l"(a), "l"(b));
}
__device__ __forceinline__ ull pack2(float lo, float hi) {
    ull r; asm("mov.b64 %0, {%1, %2};" : "=l"(r) : "f"(lo), "f"(hi)); return r;
}
__device__ __forceinline__ float2 unpack2(ull v) {
    float2 r; asm("mov.b64 {%0, %1}, %2;" : "=f"(r.x), "=f"(r.y) : "l"(v)); return r;
}

__global__ __launch_bounds__(256, 2) void mlp_kernel(
    const float* __restrict__ W_down,   // [128,256]
    const float* __restrict__ Ws,       // [3,256,256]
    const float* __restrict__ bs,       // [3,256]
    float* __restrict__ out,            // [num_nodes,256]
    int num_nodes) {

    __shared__ __align__(16) float s_act[OUTD * NTP];   // 36 KB

    int t = threadIdx.x;                 // output column
    int node0 = blockIdx.x * NT;

    // Load h128 tile (transpose to [k][node]); coalesced over k.
    for (int idx = t; idx < HID * NT; idx += 256) {
        int n = idx >> 7;         // idx / 128
        int k = idx & (HID - 1);
        int node = node0 + n;
        s_act[k * NTP + n] = (node < num_nodes) ? g_h128[(size_t)node * HID + k] : 0.f;
    }
    __syncthreads();

    ull acc[NT / 2];

    // ---- Layer 0: down projection [128 -> 256], no bias, no activation ----
    #pragma unroll
    for (int j = 0; j < NT / 2; j++) acc[j] = 0ull;
    {
        const float* W = W_down;
        #pragma unroll 4
        for (int k = 0; k < HID; k++) {
            float w = W[k * OUTD + t];
            ull wp = pack2(w, w);
            const ulonglong2* row = reinterpret_cast<const ulonglong2*>(s_act + k * NTP);
            #pragma unroll
            for (int j = 0; j < 8; j++) {
                ulonglong2 v = row[j];                  // broadcast LDS.128: nodes 4j..4j+3
                fma2(acc[2 * j],     v.x, wp);
                fma2(acc[2 * j + 1], v.y, wp);
            }
        }
    }

    // ---- Layers 1..3: h = silu(h @ Ws[L] + bs[L]) ----
    for (int L = 0; L < 3; L++) {
        __syncthreads();                 // everyone done reading previous act
        float* myrow = s_act + t * NTP;  // thread t owns row t of next input
        #pragma unroll
        for (int j = 0; j < NT / 2; j++) {
            float2 f = unpack2(acc[j]);
            myrow[2 * j]     = f.x;
            myrow[2 * j + 1] = f.y;
        }
        __syncthreads();

        float b = bs[L * OUTD + t];
        #pragma unroll
        for (int j = 0; j < NT / 2; j++) acc[j] = pack2(b, b);

        const float* W = Ws + (size_t)L * OUTD * OUTD;
        #pragma unroll 4
        for (int k = 0; k < OUTD; k++) {
            float w = W[k * OUTD + t];
            ull wp = pack2(w, w);
            const ulonglong2* row = reinterpret_cast<const ulonglong2*>(s_act + k * NTP);
            #pragma unroll
            for (int j = 0; j < 8; j++) {
                ulonglong2 v = row[j];
                fma2(acc[2 * j],     v.x, wp);
                fma2(acc[2 * j + 1], v.y, wp);
            }
        }
        // SiLU
        #pragma unroll
        for (int j = 0; j < NT / 2; j++) {
            float2 f = unpack2(acc[j]);
            f.x = f.x / (1.0f + __expf(-f.x));
            f.y = f.y / (1.0f + __expf(-f.y));
            acc[j] = pack2(f.x, f.y);
        }
    }

    // ---- Store ----
    #pragma unroll
    for (int j = 0; j < NT / 2; j++) {
        float2 f = unpack2(acc[j]);
        int n0 = node0 + 2 * j;
        int n1 = n0 + 1;
        if (n0 < num_nodes) out[(size_t)n0 * OUTD + t] = f.x;
        if (n1 < num_nodes) out[(size_t)n1 * OUTD + t] = f.y;
    }
}

// ---------------------------------------------------------------------------
// Launch: zero+detect -> gate/scatter -> fused MLP.  Graph-capturable: kernel
// launches only, no allocs, no syncs.
// ---------------------------------------------------------------------------
extern "C" void kernel_launch(void* const* d_in, const int* in_sizes, int n_in,
                              void* d_out, int out_size) {
    const float* x      = (const float*)d_in[0];   // [E,128]
    const float* rbf    = (const float*)d_in[1];   // [E,6]
    const void*  idx    =               d_in[2];   // [E] int32/int64 (auto-detected)
    const float* W_rbf  = (const float*)d_in[3];   // [6,128]
    const float* W_down = (const float*)d_in[4];   // [128,256]
    const float* Ws     = (const float*)d_in[5];   // [3,256,256]
    const float* bs     = (const float*)d_in[6];   // [3,256]
    float* out = (float*)d_out;

    int E = in_sizes[0] / HID;
    int num_nodes = out_size / OUTD;

    zero_detect_kernel<<<1024, 256>>>(idx, num_nodes);

    int gblocks = (E + 7) / 8;                       // one warp per edge
    gate_scatter_kernel<<<gblocks, 256>>>((const float4*)x, rbf, idx, W_rbf, E, num_nodes);

    int mblocks = (num_nodes + NT - 1) / NT;
    mlp_kernel<<<mblocks, 256>>>(W_down, Ws, bs, out, num_nodes);
}

// round 7
// speedup vs baseline: 1.1723x; 1.1723x over previous
#include <cuda_runtime.h>
#include <cstdint>
#include <cstddef>

#define HID   128
#define OUTD  256
#define NT    32          // nodes per MLP block
#define NTP   36          // padded node stride in smem
#define N_NODES_MAX 50000

typedef unsigned long long ull;

// Scratch: node accumulator [num_nodes, 128]. Static device array (no allocs allowed).
__device__ float g_h128[(size_t)N_NODES_MAX * HID];
__device__ int   g_is64;

// ---------------------------------------------------------------------------
// Kernel 0: zero accumulator + detect index dtype (int64 vs int32).
// ---------------------------------------------------------------------------
__global__ void zero_detect_kernel(const void* __restrict__ idx, int num_nodes) {
    size_t total  = (size_t)num_nodes * HID;
    size_t stride = (size_t)gridDim.x * blockDim.x;
    for (size_t j = (size_t)blockIdx.x * blockDim.x + threadIdx.x; j < total; j += stride)
        g_h128[j] = 0.0f;
    if (blockIdx.x == 0 && threadIdx.x == 0) {
        const long long* p = (const long long*)idx;
        int ok = 1;
        #pragma unroll
        for (int k = 0; k < 4; k++) {
            long long v = p[k];
            if (v < 0 || v >= (long long)num_nodes) ok = 0;
        }
        g_is64 = ok;
    }
}

// ---------------------------------------------------------------------------
// Kernel 1: gate + vector-red scatter.  One warp per edge.
//   coef[h] = sum_r rbf[e,r] * W_rbf[r,h];  g = coef * x[e,:]
// Lane l handles columns 4l..4l+3.  Single red.global.add.v4.f32 per lane
// (16B, 16B-aligned) replaces 4 scalar atomicAdds -> 4x fewer red ops.
// ---------------------------------------------------------------------------
__global__ void gate_scatter_kernel(const float4* __restrict__ x4,
                                    const float*  __restrict__ rbf,
                                    const void*   __restrict__ idx,
                                    const float*  __restrict__ W_rbf,
                                    int E, int num_nodes) {
    __shared__ __align__(16) float sW[6 * HID];
    for (int j = threadIdx.x; j < 6 * HID; j += blockDim.x) sW[j] = W_rbf[j];
    __syncthreads();

    int lane = threadIdx.x & 31;
    int gw = (blockIdx.x * blockDim.x + threadIdx.x) >> 5;
    if (gw >= E) return;
    int e = gw;

    int node = g_is64 ? (int)(((const long long*)idx)[e])
                      : (((const int*)idx)[e]);

    float r[6];
    #pragma unroll
    for (int q = 0; q < 6; q++) r[q] = __ldg(rbf + (size_t)e * 6 + q);

    float4 c = make_float4(0.f, 0.f, 0.f, 0.f);
    #pragma unroll
    for (int q = 0; q < 6; q++) {
        float4 wv = reinterpret_cast<const float4*>(sW + q * HID)[lane];
        c.x += r[q] * wv.x;  c.y += r[q] * wv.y;
        c.z += r[q] * wv.z;  c.w += r[q] * wv.w;
    }

    float4 xv = __ldg(x4 + (size_t)e * (HID / 4) + lane);
    float* dst = g_h128 + (size_t)node * HID + lane * 4;   // 16B aligned
    asm volatile("red.global.add.v4.f32 [%0], {%1, %2, %3, %4};"
                 :: "l"(dst),
                    "f"(c.x * xv.x), "f"(c.y * xv.y),
                    "f"(c.z * xv.z), "f"(c.w * xv.w)
                 : "memory");
}

// ---------------------------------------------------------------------------
// Kernel 2: fused node MLP.  Block = 256 threads (thread t owns output col t),
// 32 nodes per block.  Activations in smem as [k][node] (stride NTP=36); one
// broadcast LDS.128 yields 4 node-values = 2 packed f32x2 operands.
// fma.rn.f32x2 doubles fp32 FMA throughput vs scalar FFMA.
// ---------------------------------------------------------------------------
__device__ __forceinline__ void fma2(ull& acc, ull a, ull b) {
    asm("fma.rn.f32x2 %0, %1, %2, %0;" : "+l"(acc) : "l"(a), "l"(b));
}
__device__ __forceinline__ ull pack2(float lo, float hi) {
    ull r; asm("mov.b64 %0, {%1, %2};" : "=l"(r) : "f"(lo), "f"(hi)); return r;
}
__device__ __forceinline__ float2 unpack2(ull v) {
    float2 r; asm("mov.b64 {%0, %1}, %2;" : "=f"(r.x), "=f"(r.y) : "l"(v)); return r;
}

__global__ __launch_bounds__(256, 3) void mlp_kernel(
    const float* __restrict__ W_down,   // [128,256]
    const float* __restrict__ Ws,       // [3,256,256]
    const float* __restrict__ bs,       // [3,256]
    float* __restrict__ out,            // [num_nodes,256]
    int num_nodes) {

    __shared__ __align__(16) float s_act[OUTD * NTP];   // 36 KB

    int t = threadIdx.x;                 // output column
    int node0 = blockIdx.x * NT;

    // Load h128 tile (transpose to [k][node]); coalesced over k.
    for (int idx = t; idx < HID * NT; idx += 256) {
        int n = idx >> 7;         // idx / 128
        int k = idx & (HID - 1);
        int node = node0 + n;
        s_act[k * NTP + n] = (node < num_nodes) ? g_h128[(size_t)node * HID + k] : 0.f;
    }
    __syncthreads();

    ull acc[NT / 2];

    // ---- Layer 0: down projection [128 -> 256], no bias, no activation ----
    #pragma unroll
    for (int j = 0; j < NT / 2; j++) acc[j] = 0ull;
    {
        const float* W = W_down;
        #pragma unroll 4
        for (int k = 0; k < HID; k++) {
            float w = W[k * OUTD + t];
            ull wp = pack2(w, w);
            const ulonglong2* row = reinterpret_cast<const ulonglong2*>(s_act + k * NTP);
            #pragma unroll
            for (int j = 0; j < 8; j++) {
                ulonglong2 v = row[j];                  // broadcast LDS.128: nodes 4j..4j+3
                fma2(acc[2 * j],     v.x, wp);
                fma2(acc[2 * j + 1], v.y, wp);
            }
        }
    }

    // ---- Layers 1..3: h = silu(h @ Ws[L] + bs[L]) ----
    for (int L = 0; L < 3; L++) {
        __syncthreads();                 // everyone done reading previous act
        float* myrow = s_act + t * NTP;  // thread t owns row t of next input
        #pragma unroll
        for (int j = 0; j < NT / 2; j++) {
            float2 f = unpack2(acc[j]);
            myrow[2 * j]     = f.x;
            myrow[2 * j + 1] = f.y;
        }
        __syncthreads();

        float b = bs[L * OUTD + t];
        #pragma unroll
        for (int j = 0; j < NT / 2; j++) acc[j] = pack2(b, b);

        const float* W = Ws + (size_t)L * OUTD * OUTD;
        #pragma unroll 4
        for (int k = 0; k < OUTD; k++) {
            float w = W[k * OUTD + t];
            ull wp = pack2(w, w);
            const ulonglong2* row = reinterpret_cast<const ulonglong2*>(s_act + k * NTP);
            #pragma unroll
            for (int j = 0; j < 8; j++) {
                ulonglong2 v = row[j];
                fma2(acc[2 * j],     v.x, wp);
                fma2(acc[2 * j + 1], v.y, wp);
            }
        }
        // SiLU
        #pragma unroll
        for (int j = 0; j < NT / 2; j++) {
            float2 f = unpack2(acc[j]);
            f.x = f.x / (1.0f + __expf(-f.x));
            f.y = f.y / (1.0f + __expf(-f.y));
            acc[j] = pack2(f.x, f.y);
        }
    }

    // ---- Store ----
    #pragma unroll
    for (int j = 0; j < NT / 2; j++) {
        float2 f = unpack2(acc[j]);
        int n0 = node0 + 2 * j;
        int n1 = n0 + 1;
        if (n0 < num_nodes) out[(size_t)n0 * OUTD + t] = f.x;
        if (n1 < num_nodes) out[(size_t)n1 * OUTD + t] = f.y;
    }
}

// ---------------------------------------------------------------------------
// Launch: zero+detect -> gate/scatter -> fused MLP.  Graph-capturable.
// ---------------------------------------------------------------------------
extern "C" void kernel_launch(void* const* d_in, const int* in_sizes, int n_in,
                              void* d_out, int out_size) {
    const float* x      = (const float*)d_in[0];   // [E,128]
    const float* rbf    = (const float*)d_in[1];   // [E,6]
    const void*  idx    =               d_in[2];   // [E] int32/int64 (auto-detected)
    const float* W_rbf  = (const float*)d_in[3];   // [6,128]
    const float* W_down = (const float*)d_in[4];   // [128,256]
    const float* Ws     = (const float*)d_in[5];   // [3,256,256]
    const float* bs     = (const float*)d_in[6];   // [3,256]
    float* out = (float*)d_out;

    int E = in_sizes[0] / HID;
    int num_nodes = out_size / OUTD;

    zero_detect_kernel<<<1024, 256>>>(idx, num_nodes);

    int gblocks = (E + 7) / 8;                       // one warp per edge
    gate_scatter_kernel<<<gblocks, 256>>>((const float4*)x, rbf, idx, W_rbf, E, num_nodes);

    int mblocks = (num_nodes + NT - 1) / NT;
    mlp_kernel<<<mblocks, 256>>>(W_down, Ws, bs, out, num_nodes);
}

// round 10
// speedup vs baseline: 2.4037x; 2.0503x over previous
#include <cuda_runtime.h>
#include <cuda_bf16.h>
#include <cstdint>
#include <cstddef>

#define HID   128
#define OUTD  256
#define N_NODES_MAX 50000

// MMA MLP tiling
#define TILE_M   128
#define NCHUNK   14            // K-chunks of 64: layer0(K=128)=2, layers1-3(K=256)=4 each
#define AROWB    528           // A smem row stride bytes (264 bf16, K<=256 + pad8)
#define BROWB    144           // B smem row stride bytes (72 bf16, K=64 + pad8)
#define CHUNK_B  (OUTD * BROWB)        // 36864 bytes per weight chunk plane
// smem offsets
#define OFF_AH   0
#define OFF_AL   (TILE_M * AROWB)              // 67584
#define OFF_BH   (2 * TILE_M * AROWB)          // 135168
#define OFF_BL   (2 * TILE_M * AROWB + CHUNK_B)        // 172032
#define OFF_BIAS (2 * TILE_M * AROWB + 2 * CHUNK_B)    // 208896
#define SMEM_REQ (OFF_BIAS + 3 * OUTD * 4 + 128)       // ~212 KB

typedef unsigned long long ull;

// ---------------------------------------------------------------------------
// Device globals (no allocs allowed)
// ---------------------------------------------------------------------------
__device__ float g_h128[(size_t)N_NODES_MAX * HID];
__device__ int   g_is64;
__device__ __align__(16) unsigned char g_Bh[NCHUNK * CHUNK_B];  // bf16 hi weight images
__device__ __align__(16) unsigned char g_Bl[NCHUNK * CHUNK_B];  // bf16 lo weight images

// ---------------------------------------------------------------------------
// Helpers
// ---------------------------------------------------------------------------
__device__ __forceinline__ uint32_t smem_u32(const void* p) {
    uint32_t a;
    asm("{ .reg .u64 t; cvta.to.shared.u64 t, %1; cvt.u32.u64 %0, t; }" : "=r"(a) : "l"(p));
    return a;
}
__device__ __forceinline__ void cp_async16(uint32_t saddr, const void* gaddr) {
    asm volatile("cp.async.cg.shared.global [%0], [%1], 16;" :: "r"(saddr), "l"(gaddr));
}
__device__ __forceinline__ void ldsm_x4(uint32_t addr, uint32_t r[4]) {
    asm volatile("ldmatrix.sync.aligned.m8n8.x4.shared.b16 {%0,%1,%2,%3}, [%4];"
        : "=r"(r[0]), "=r"(r[1]), "=r"(r[2]), "=r"(r[3]) : "r"(addr));
}
__device__ __forceinline__ void mma_bf16(float* c, const uint32_t* a, uint32_t b0, uint32_t b1) {
    asm volatile("mma.sync.aligned.m16n8k16.row.col.f32.bf16.bf16.f32 "
        "{%0,%1,%2,%3}, {%4,%5,%6,%7}, {%8,%9}, {%0,%1,%2,%3};"
        : "+f"(c[0]), "+f"(c[1]), "+f"(c[2]), "+f"(c[3])
        : "r"(a[0]), "r"(a[1]), "r"(a[2]), "r"(a[3]), "r"(b0), "r"(b1));
}
__device__ __forceinline__ void bf16split(float v, unsigned short& h, unsigned short& l) {
    __nv_bfloat16 hb = __float2bfloat16(v);
    __nv_bfloat16 lb = __float2bfloat16(v - __bfloat162float(hb));
    h = __bfloat16_as_ushort(hb);
    l = __bfloat16_as_ushort(lb);
}
__device__ __forceinline__ uint32_t packsplit_hi(float a, float b) {
    unsigned short h0, l0, h1, l1;
    bf16split(a, h0, l0); bf16split(b, h1, l1);
    return (uint32_t)h0 | ((uint32_t)h1 << 16);
}
__device__ __forceinline__ uint32_t packsplit_lo(float a, float b) {
    unsigned short h0, l0, h1, l1;
    bf16split(a, h0, l0); bf16split(b, h1, l1);
    return (uint32_t)l0 | ((uint32_t)l1 << 16);
}

// ---------------------------------------------------------------------------
// Kernel 0: zero accumulator + detect index dtype (int64 vs int32).
// ---------------------------------------------------------------------------
__global__ void zero_detect_kernel(const void* __restrict__ idx, int num_nodes) {
    size_t total  = (size_t)num_nodes * HID;
    size_t stride = (size_t)gridDim.x * blockDim.x;
    for (size_t j = (size_t)blockIdx.x * blockDim.x + threadIdx.x; j < total; j += stride)
        g_h128[j] = 0.0f;
    if (blockIdx.x == 0 && threadIdx.x == 0) {
        const long long* p = (const long long*)idx;
        int ok = 1;
        #pragma unroll
        for (int k = 0; k < 4; k++) {
            long long v = p[k];
            if (v < 0 || v >= (long long)num_nodes) ok = 0;
        }
        g_is64 = ok;
    }
}

// ---------------------------------------------------------------------------
// Kernel 0b: weight prep — fp32 -> bf16 hi/lo, [N,K]-row-major padded chunk
// images so the MLP kernel cp.asyncs them verbatim into smem.
// chunk c: layer L(c), K-slice of 64.  image[n][kk] = W[k_base+kk][n].
// ---------------------------------------------------------------------------
__global__ void weight_prep_kernel(const float* __restrict__ W_down,
                                   const float* __restrict__ Ws) {
    int idx = blockIdx.x * blockDim.x + threadIdx.x;   // 14*64*256
    if (idx >= NCHUNK * 64 * OUTD) return;
    int n  = idx & 255;
    int kk = (idx >> 8) & 63;
    int c  = idx >> 14;
    int L, k;
    if (c < 2) { L = 0; k = c * 64 + kk; }
    else       { L = 1 + (c - 2) / 4; k = ((c - 2) & 3) * 64 + kk; }
    float w = (L == 0) ? W_down[k * OUTD + n]
                       : Ws[(size_t)(L - 1) * OUTD * OUTD + k * OUTD + n];
    unsigned short h, l;
    bf16split(w, h, l);
    size_t off = (size_t)c * CHUNK_B + (size_t)n * BROWB + kk * 2;
    *(unsigned short*)(g_Bh + off) = h;
    *(unsigned short*)(g_Bl + off) = l;
}

// ---------------------------------------------------------------------------
// Kernel 1: gate + vector-red scatter (unchanged from passing R7 kernel).
// ---------------------------------------------------------------------------
__global__ void gate_scatter_kernel(const float4* __restrict__ x4,
                                    const float*  __restrict__ rbf,
                                    const void*   __restrict__ idx,
                                    const float*  __restrict__ W_rbf,
                                    int E, int num_nodes) {
    __shared__ __align__(16) float sW[6 * HID];
    for (int j = threadIdx.x; j < 6 * HID; j += blockDim.x) sW[j] = W_rbf[j];
    __syncthreads();

    int lane = threadIdx.x & 31;
    int gw = (blockIdx.x * blockDim.x + threadIdx.x) >> 5;
    if (gw >= E) return;
    int e = gw;

    int node = g_is64 ? (int)(((const long long*)idx)[e])
                      : (((const int*)idx)[e]);

    float r[6];
    #pragma unroll
    for (int q = 0; q < 6; q++) r[q] = __ldg(rbf + (size_t)e * 6 + q);

    float4 c = make_float4(0.f, 0.f, 0.f, 0.f);
    #pragma unroll
    for (int q = 0; q < 6; q++) {
        float4 wv = reinterpret_cast<const float4*>(sW + q * HID)[lane];
        c.x += r[q] * wv.x;  c.y += r[q] * wv.y;
        c.z += r[q] * wv.z;  c.w += r[q] * wv.w;
    }

    float4 xv = __ldg(x4 + (size_t)e * (HID / 4) + lane);
    float* dst = g_h128 + (size_t)node * HID + lane * 4;
    asm volatile("red.global.add.v4.f32 [%0], {%1, %2, %3, %4};"
                 :: "l"(dst),
                    "f"(c.x * xv.x), "f"(c.y * xv.y),
                    "f"(c.z * xv.z), "f"(c.w * xv.w)
                 : "memory");
}

// ---------------------------------------------------------------------------
// Kernel 2: fused MLP on HMMA (mma.sync m16n8k16 bf16, fp32 accum).
// CTA = 128 nodes x 256 outs, 512 threads, warp grid 4(M) x 4(N),
// warp tile 32x64.  A in smem as bf16 hi/lo planes; 3 MMA passes per step.
// ---------------------------------------------------------------------------
__global__ __launch_bounds__(512, 1) void mlp_mma_kernel(
    const float* __restrict__ bs, float* __restrict__ out, int num_nodes) {

    extern __shared__ __align__(16) unsigned char dsm[];
    uint32_t sb = smem_u32(dsm);
    const uint32_t sAh = sb + OFF_AH, sAl = sb + OFF_AL;
    const uint32_t sBh = sb + OFF_BH, sBl = sb + OFF_BL;
    float* sbias = (float*)(dsm + OFF_BIAS);

    int tid  = threadIdx.x;
    int lane = tid & 31;
    int wid  = tid >> 5;               // 0..15
    int wm   = wid & 3;                // warp M position
    int wn   = wid >> 2;               // warp N position
    int m0   = wm * 32;
    int n0   = wn * 64;

    for (int j = tid; j < 3 * OUTD; j += 512) sbias[j] = bs[j];

    // ---- Initial A: g_h128 fp32 -> bf16 hi/lo planes.  t -> row t/4, k-span 32.
    {
        int r  = tid >> 2;
        int kq = (tid & 3) * 32;
        int node = blockIdx.x * TILE_M + r;
        bool v = node < num_nodes;
        const float4* src = (const float4*)(g_h128 + (size_t)node * HID + kq);
        unsigned char* rowh = dsm + OFF_AH + r * AROWB + kq * 2;
        unsigned char* rowl = dsm + OFF_AL + r * AROWB + kq * 2;
        #pragma unroll
        for (int i = 0; i < 8; i++) {
            float4 f = v ? __ldg(src + i) : make_float4(0.f, 0.f, 0.f, 0.f);
            uint32_t h0 = packsplit_hi(f.x, f.y), h1 = packsplit_hi(f.z, f.w);
            uint32_t l0 = packsplit_lo(f.x, f.y), l1 = packsplit_lo(f.z, f.w);
            ((uint32_t*)(rowh + i * 8))[0] = h0;  ((uint32_t*)(rowh + i * 8))[1] = h1;
            ((uint32_t*)(rowl + i * 8))[0] = l0;  ((uint32_t*)(rowl + i * 8))[1] = l1;
        }
    }
    __syncthreads();

    const int nchunks[4] = {2, 4, 4, 4};
    const int cbase[4]   = {0, 2, 6, 10};

    // ldmatrix lane addressing: row = base + (lane&15), col += 8 if lane>=16
    int lrow = lane & 15;
    int lcol = (lane >> 4) << 3;

    for (int L = 0; L < 4; L++) {
        float acc[2][8][4];
        #pragma unroll
        for (int a = 0; a < 2; a++)
            #pragma unroll
            for (int b = 0; b < 8; b++)
                #pragma unroll
                for (int q = 0; q < 4; q++) acc[a][b][q] = 0.f;

        for (int cc = 0; cc < nchunks[L]; cc++) {
            __syncthreads();                       // B smem free / A writes visible
            int c = cbase[L] + cc;
            const uint4* gh = (const uint4*)(g_Bh + (size_t)c * CHUNK_B);
            const uint4* gl = (const uint4*)(g_Bl + (size_t)c * CHUNK_B);
            for (int j = tid; j < CHUNK_B / 16; j += 512) {
                cp_async16(sBh + j * 16, gh + j);
                cp_async16(sBl + j * 16, gl + j);
            }
            asm volatile("cp.async.commit_group;");
            asm volatile("cp.async.wait_group 0;" ::: "memory");
            __syncthreads();

            #pragma unroll
            for (int ks = 0; ks < 4; ks++) {
                int ka = cc * 64 + ks * 16;        // A column (layer-K space)
                int kb = ks * 16;                  // B column (chunk-K space)
                uint32_t ah[2][4], al[2][4];
                #pragma unroll
                for (int mf = 0; mf < 2; mf++) {
                    uint32_t ro = (uint32_t)(m0 + mf * 16 + lrow) * AROWB + (ka + lcol) * 2;
                    ldsm_x4(sAh + ro, ah[mf]);
                    ldsm_x4(sAl + ro, al[mf]);
                }
                #pragma unroll
                for (int p = 0; p < 4; p++) {
                    uint32_t bo = (uint32_t)(n0 + p * 16 + lrow) * BROWB + (kb + lcol) * 2;
                    uint32_t bh[4], bl[4];
                    ldsm_x4(sBh + bo, bh);
                    ldsm_x4(sBl + bo, bl);
                    #pragma unroll
                    for (int mf = 0; mf < 2; mf++) {
                        float* c0 = acc[mf][2 * p];
                        float* c1 = acc[mf][2 * p + 1];
                        mma_bf16(c0, ah[mf], bh[0], bh[2]);   // Ah*Bh
                        mma_bf16(c0, ah[mf], bl[0], bl[2]);   // Ah*Bl
                        mma_bf16(c0, al[mf], bh[0], bh[2]);   // Al*Bh
                        mma_bf16(c1, ah[mf], bh[1], bh[3]);
                        mma_bf16(c1, ah[mf], bl[1], bl[3]);
                        mma_bf16(c1, al[mf], bh[1], bh[3]);
                    }
                }
            }
        }
        __syncthreads();                           // all reads of A done

        // ---- Epilogue: (bias+SiLU for L>=1), then next-A planes or gmem out
        #pragma unroll
        for (int mf = 0; mf < 2; mf++) {
            #pragma unroll
            for (int nf = 0; nf < 8; nf++) {
                int n = n0 + nf * 8 + 2 * (lane & 3);
                #pragma unroll
                for (int h2 = 0; h2 < 2; h2++) {
                    int row = m0 + mf * 16 + (lane >> 2) + h2 * 8;
                    float v0 = acc[mf][nf][2 * h2];
                    float v1 = acc[mf][nf][2 * h2 + 1];
                    if (L >= 1) {
                        float t0 = v0 + sbias[(L - 1) * OUTD + n];
                        float t1 = v1 + sbias[(L - 1) * OUTD + n + 1];
                        v0 = t0 / (1.0f + __expf(-t0));
                        v1 = t1 / (1.0f + __expf(-t1));
                    }
                    if (L < 3) {
                        *(uint32_t*)(dsm + OFF_AH + row * AROWB + n * 2) = packsplit_hi(v0, v1);
                        *(uint32_t*)(dsm + OFF_AL + row * AROWB + n * 2) = packsplit_lo(v0, v1);
                    } else {
                        int node = blockIdx.x * TILE_M + row;
                        if (node < num_nodes)
                            *(float2*)(out + (size_t)node * OUTD + n) = make_float2(v0, v1);
                    }
                }
            }
        }
        // next layer's first chunk barrier orders these writes before reads
    }
}

// ---------------------------------------------------------------------------
// Launch: zero+detect -> weight prep -> gate/scatter -> HMMA MLP.
// Graph-capturable: kernel launches only.
// ---------------------------------------------------------------------------
extern "C" void kernel_launch(void* const* d_in, const int* in_sizes, int n_in,
                              void* d_out, int out_size) {
    const float* x      = (const float*)d_in[0];   // [E,128]
    const float* rbf    = (const float*)d_in[1];   // [E,6]
    const void*  idx    =               d_in[2];   // [E] int32/int64 (auto-detected)
    const float* W_rbf  = (const float*)d_in[3];   // [6,128]
    const float* W_down = (const float*)d_in[4];   // [128,256]
    const float* Ws     = (const float*)d_in[5];   // [3,256,256]
    const float* bs     = (const float*)d_in[6];   // [3,256]
    float* out = (float*)d_out;

    int E = in_sizes[0] / HID;
    int num_nodes = out_size / OUTD;

    static int smem_set = 0;
    if (!smem_set) {
        cudaFuncSetAttribute(mlp_mma_kernel,
                             cudaFuncAttributeMaxDynamicSharedMemorySize, SMEM_REQ);
        smem_set = 1;
    }

    zero_detect_kernel<<<1024, 256>>>(idx, num_nodes);

    int pthreads = NCHUNK * 64 * OUTD;
    weight_prep_kernel<<<(pthreads + 255) / 256, 256>>>(W_down, Ws);

    int gblocks = (E + 7) / 8;                       // one warp per edge
    gate_scatter_kernel<<<gblocks, 256>>>((const float4*)x, rbf, idx, W_rbf, E, num_nodes);

    int mblocks = (num_nodes + TILE_M - 1) / TILE_M;
    mlp_mma_kernel<<<mblocks, 512, SMEM_REQ>>>(bs, out, num_nodes);
}